// round 12
// baseline (speedup 1.0000x reference)
#include <cuda_runtime.h>
#include <cstdint>

// FPS B=16, N=65536, S=2048, out = coords of selected (B,S,3) f32.
// R10: 8 clusters x 8 CTAs; each cluster software-pipelines TWO batches so
// batch A's DSMEM exchange flight hides behind batch B's compute (and vice
// versa). Per-batch logic identical to R9 (3504us): negated coords SoA in
// smem -> ulonglong2 -> packed add/mul.rn.f32x2 (per-lane IEEE RN, bit-
// identical); value-only max (redux.sync) + parallel-min rescan for exact
// first-index argmax; split-u32 redux CTA reduce; v2.b64 DSMEM push +
// parity mbarrier.

#define NBATCH   16
#define NPTS     65536
#define NSAMP    2048
#define CLUSTER  8
#define NPC      (NPTS / CLUSTER)     // 8192
#define THREADS  512
#define NWARPS   (THREADS / 32)       // 16
#define PPT      (NPC / THREADS)      // 16
#define GROUPS   (PPT / 4)            // 4

typedef unsigned long long u64;

// 32-byte slot: key @0 (16-aligned), xy packed @8, z @16.
struct __align__(16) Slot { u64 key; u64 xy; float z; float pad[3]; };

struct __align__(16) Smem {
    float xA[NPC]; float yA[NPC]; float zA[NPC];   // negated coords, batch A
    float xB[NPC]; float yB[NPC]; float zB[NPC];   // negated coords, batch B
    u64   wkey[NWARPS];          // per-warp packed (valBits<<32)|~localIdx (reused A/B)
    Slot  slotsA[2][CLUSTER];    // parity-double-buffered cluster exchange
    Slot  slotsB[2][CLUSTER];
    u64   mbarA;
    u64   mbarB;
};

__device__ __forceinline__ uint32_t smem_u32(const void* p) {
    return (uint32_t)__cvta_generic_to_shared(p);
}
__device__ __forceinline__ u64 pk2(float lo, float hi) {
    u64 r; asm("mov.b64 %0, {%1, %2};" : "=l"(r) : "f"(lo), "f"(hi)); return r;
}
__device__ __forceinline__ void upk2(float& lo, float& hi, u64 v) {
    asm("mov.b64 {%0, %1}, %2;" : "=f"(lo), "=f"(hi) : "l"(v));
}
__device__ __forceinline__ u64 add2(u64 a, u64 b) {
    u64 r; asm("add.rn.f32x2 %0, %1, %2;" : "=l"(r) : "l"(a), "l"(b)); return r;
}
__device__ __forceinline__ u64 mul2(u64 a, u64 b) {
    u64 r; asm("mul.rn.f32x2 %0, %1, %2;" : "=l"(r) : "l"(a), "l"(b)); return r;
}
__device__ __forceinline__ unsigned redux_max(unsigned v) {
    unsigned r; asm("redux.sync.max.u32 %0, %1, 0xffffffff;" : "=r"(r) : "r"(v)); return r;
}
__device__ __forceinline__ unsigned redux_min(unsigned v) {
    unsigned r; asm("redux.sync.min.u32 %0, %1, 0xffffffff;" : "=r"(r) : "r"(v)); return r;
}

// Distance update + running min over this thread's 16 points; returns packed
// warp-level (valBits<<32)|~minIdx key via redux. Identical math to R9.
__device__ __forceinline__ u64 compute_phase(
    const float* __restrict__ sx_arr, const float* __restrict__ sy_arr,
    const float* __restrict__ sz_arr, float (&closest)[PPT],
    float sx, float sy, float sz, int tid)
{
    u64 sxx = pk2(sx, sx), syy = pk2(sy, sy), szz = pk2(sz, sz);
    float vmax = 0.0f;
    #pragma unroll
    for (int g = 0; g < GROUPS; ++g) {
        const int bi = g * (THREADS * 4) + tid * 4;
        ulonglong2 X = *reinterpret_cast<const ulonglong2*>(&sx_arr[bi]);
        ulonglong2 Y = *reinterpret_cast<const ulonglong2*>(&sy_arr[bi]);
        ulonglong2 Z = *reinterpret_cast<const ulonglong2*>(&sz_arr[bi]);
        {
            u64 dx = add2(sxx, X.x);
            u64 dy = add2(syy, Y.x);
            u64 dz = add2(szz, Z.x);
            u64 d  = add2(add2(mul2(dx, dx), mul2(dy, dy)), mul2(dz, dz));
            float d0, d1; upk2(d0, d1, d);
            float c0 = fminf(closest[g*4+0], d0); closest[g*4+0] = c0;
            float c1 = fminf(closest[g*4+1], d1); closest[g*4+1] = c1;
            vmax = fmaxf(vmax, c0); vmax = fmaxf(vmax, c1);
        }
        {
            u64 dx = add2(sxx, X.y);
            u64 dy = add2(syy, Y.y);
            u64 dz = add2(szz, Z.y);
            u64 d  = add2(add2(mul2(dx, dx), mul2(dy, dy)), mul2(dz, dz));
            float d0, d1; upk2(d0, d1, d);
            float c0 = fminf(closest[g*4+2], d0); closest[g*4+2] = c0;
            float c1 = fminf(closest[g*4+3], d1); closest[g*4+3] = c1;
            vmax = fmaxf(vmax, c0); vmax = fmaxf(vmax, c1);
        }
    }

    const unsigned wmax = redux_max(__float_as_uint(vmax));
    unsigned my = 0xffffffffu;
    #pragma unroll
    for (int g = 0; g < GROUPS; ++g) {
        #pragma unroll
        for (int j = 0; j < 4; ++j) {
            unsigned cand = (unsigned)(g * (THREADS * 4) + tid * 4 + j);
            if (__float_as_uint(closest[g*4+j]) == wmax)
                my = (cand < my) ? cand : my;
        }
    }
    const unsigned wmin = redux_min(my);
    return ((u64)wmax << 32) | (u64)(unsigned)(~wmin);
}

// Warp 0: CTA reduce over wkey (split-u32 redux) + DSMEM push to all peers.
__device__ __forceinline__ void reduce_and_push(
    Smem& s, const float* __restrict__ sx_arr, const float* __restrict__ sy_arr,
    const float* __restrict__ sz_arr, Slot* slot_self, uint32_t mb_self,
    int lane, int rank)
{
    u64 wk = (lane < NWARPS) ? s.wkey[lane] : 0ull;
    unsigned vhi = (unsigned)(wk >> 32);
    unsigned vlo = (unsigned)wk;                       // ~localIdx
    unsigned Vmax = redux_max(vhi);
    unsigned nli  = redux_max((vhi == Vmax) ? vlo : 0u);   // max ~idx = min idx
    if (lane < CLUSTER) {
        unsigned li   = ~nli;
        unsigned gidx = (unsigned)rank * NPC + li;
        u64 ckey = ((u64)Vmax << 32) | (u64)(unsigned)(~gidx);
        float cx = -sx_arr[li], cy = -sy_arr[li], cz = -sz_arr[li];   // un-negate
        u64 xy = pk2(cx, cy);
        uint32_t sl = smem_u32(slot_self);
        uint32_t rs, rb;
        asm volatile("mapa.shared::cluster.u32 %0, %1, %2;" : "=r"(rs) : "r"(sl),      "r"(lane));
        asm volatile("mapa.shared::cluster.u32 %0, %1, %2;" : "=r"(rb) : "r"(mb_self), "r"(lane));
        asm volatile("st.shared::cluster.v2.b64 [%0], {%1, %2};"
                     :: "r"(rs), "l"(ckey), "l"(xy) : "memory");
        asm volatile("st.shared::cluster.f32 [%0+16], %1;" :: "r"(rs), "f"(cz) : "memory");
        asm volatile("mbarrier.arrive.release.cluster.shared::cluster.b64 _, [%0];"
                     :: "r"(rb) : "memory");
    }
}

__device__ __forceinline__ void wait_and_scan(
    uint32_t mb_addr, const Slot* sl, int parity,
    float& nsx, float& nsy, float& nsz)
{
    asm volatile(
        "{\n\t.reg .pred P;\n"
        "W%=:\n\t"
        "mbarrier.try_wait.parity.acquire.cluster.shared::cta.b64 P, [%0], %1, 0x989680;\n\t"
        "@P bra.uni D%=;\n\t"
        "bra.uni W%=;\n"
        "D%=:\n\t}"
        :: "r"(mb_addr), "r"(parity) : "memory");

    u64 bk = sl[0].key;
    int br = 0;
    #pragma unroll
    for (int r = 1; r < CLUSTER; ++r) {
        u64 kr = sl[r].key;
        if (kr > bk) { bk = kr; br = r; }
    }
    upk2(nsx, nsy, sl[br].xy);
    nsz = sl[br].z;
}

__global__ void __launch_bounds__(THREADS, 1)
fps_kernel(const float* __restrict__ pc, float* __restrict__ out)
{
    extern __shared__ char smraw[];
    Smem& s = *reinterpret_cast<Smem*>(smraw);

    const int tid  = threadIdx.x;
    const int lane = tid & 31;
    const int warp = tid >> 5;
    const int rank = blockIdx.x & (CLUSTER - 1);
    const int pair = blockIdx.x >> 3;         // 0..7
    const int bA   = pair * 2;
    const int bB   = pair * 2 + 1;

    const float* __restrict__ baseA = pc + (size_t)bA * NPTS * 3;
    const float* __restrict__ baseB = pc + (size_t)bB * NPTS * 3;

    // ---- prologue: stage NEGATED coords for both batches ----
    for (int i = tid; i < NPC; i += THREADS) {
        int gi = rank * NPC + i;
        s.xA[i] = -baseA[gi * 3 + 0];
        s.yA[i] = -baseA[gi * 3 + 1];
        s.zA[i] = -baseA[gi * 3 + 2];
        s.xB[i] = -baseB[gi * 3 + 0];
        s.yB[i] = -baseB[gi * 3 + 1];
        s.zB[i] = -baseB[gi * 3 + 2];
    }
    if (tid == 0) {
        asm volatile("mbarrier.init.shared.b64 [%0], %1;"
                     :: "r"(smem_u32(&s.mbarA)), "r"(CLUSTER) : "memory");
        asm volatile("mbarrier.init.shared.b64 [%0], %1;"
                     :: "r"(smem_u32(&s.mbarB)), "r"(CLUSTER) : "memory");
    }

    float closA[PPT], closB[PPT];
    #pragma unroll
    for (int i = 0; i < PPT; i++) {
        closA[i] = __int_as_float(0x7f800000);
        closB[i] = __int_as_float(0x7f800000);
    }

    float axs = baseA[0], ays = baseA[1], azs = baseA[2];  // selection A: point 0
    float bxs = baseB[0], bys = baseB[1], bzs = baseB[2];  // selection B: point 0

    __syncthreads();
    asm volatile("barrier.cluster.arrive.aligned;" ::: "memory");
    asm volatile("barrier.cluster.wait.aligned;"   ::: "memory");

    const uint32_t mbA = smem_u32(&s.mbarA);
    const uint32_t mbB = smem_u32(&s.mbarB);

    for (int it = 0; it < NSAMP; ++it) {
        const int p = it & 1;

        // ======== batch A: compute + reduce + push (exchange in flight) ========
        u64 kA = compute_phase(s.xA, s.yA, s.zA, closA, axs, ays, azs, tid);
        if (lane == 0) s.wkey[warp] = kA;
        __syncthreads();
        if (warp == 0)
            reduce_and_push(s, s.xA, s.yA, s.zA, &s.slotsA[p][rank], mbA, lane, rank);

        // ======== batch B: compute + reduce + push (hides A's flight) ========
        u64 kB = compute_phase(s.xB, s.yB, s.zB, closB, bxs, bys, bzs, tid);
        if (lane == 0) s.wkey[warp] = kB;
        __syncthreads();
        if (warp == 0)
            reduce_and_push(s, s.xB, s.yB, s.zB, &s.slotsB[p][rank], mbB, lane, rank);

        // ======== collect A then B ========
        wait_and_scan(mbA, s.slotsA[p], p, axs, ays, azs);
        if (rank == 0 && tid == 0) {
            float* o = out + ((size_t)bA * NSAMP + it) * 3;
            o[0] = axs; o[1] = ays; o[2] = azs;
        }
        wait_and_scan(mbB, s.slotsB[p], p, bxs, bys, bzs);
        if (rank == 0 && tid == 0) {
            float* o = out + ((size_t)bB * NSAMP + it) * 3;
            o[0] = bxs; o[1] = bys; o[2] = bzs;
        }
    }
}

extern "C" void kernel_launch(void* const* d_in, const int* in_sizes, int n_in,
                              void* d_out, int out_size)
{
    (void)in_sizes; (void)n_in; (void)out_size;
    const float* pc  = (const float*)d_in[0];
    float*       out = (float*)d_out;

    static bool attr_set = false;
    if (!attr_set) {
        cudaFuncSetAttribute(fps_kernel,
                             cudaFuncAttributeMaxDynamicSharedMemorySize,
                             (int)sizeof(Smem));
        attr_set = true;
    }

    cudaLaunchConfig_t cfg = {};
    cfg.gridDim = dim3((NBATCH / 2) * CLUSTER, 1, 1);   // 64 CTAs
    cfg.blockDim = dim3(THREADS, 1, 1);
    cfg.dynamicSmemBytes = sizeof(Smem);
    cfg.stream = 0;
    cudaLaunchAttribute attrs[1];
    attrs[0].id = cudaLaunchAttributeClusterDimension;
    attrs[0].val.clusterDim = {CLUSTER, 1, 1};
    cfg.attrs = attrs;
    cfg.numAttrs = 1;
    cudaLaunchKernelEx(&cfg, fps_kernel, pc, out);
}